// round 3
// baseline (speedup 1.0000x reference)
#include <cuda_runtime.h>
#include <math.h>
#include <stdint.h>

#define BATCH 8
#define DM    256
#define LSEQ  8192
#define NF    8192      /* complex FFT size (for 16384-point real FFT) */
#define FFT_THREADS 512

/* ---------------- scratch (device globals; no allocation allowed) ---------------- */
__device__ float2 g_tw8k[4096];                 /* exp(-2pi i j/8192), j<4096   */
__device__ float2 g_u16[8193];                  /* exp(-2pi i k/16384), k<=8192 */
__device__ float  g_Wt1[256 * 768];             /* in_W^T  [K=256][N=768]      */
__device__ float  g_Wt2[256 * 256];             /* out_W^T [K=256][N=256]      */
__device__ float  g_sactT[64 * LSEQ];           /* silu(t*W1+b1)^T [64][L]     */
__device__ float  g_h[DM * LSEQ];               /* implicit filter [D][L]      */
__device__ float2 g_Hf[DM * 8193];              /* rfft16384(filter) [D][8193] */
__device__ float  g_proj[(size_t)BATCH * LSEQ * 768];
__device__ float  g_v [(size_t)BATCH * DM * LSEQ];
__device__ float  g_g0[(size_t)BATCH * DM * LSEQ];
__device__ float  g_g1[(size_t)BATCH * DM * LSEQ];
__device__ float  g_yc[(size_t)BATCH * DM * LSEQ];
__device__ float  g_gated[(size_t)BATCH * LSEQ * DM];

/* ---------------- helpers ---------------- */
__device__ __forceinline__ float2 cmul(float2 a, float2 b) {
    return make_float2(a.x * b.x - a.y * b.y, a.x * b.y + a.y * b.x);
}

/* ---------------- table init (idempotent, runs every launch) ---------------- */
__global__ void init_tables_kernel() {
    int i = blockIdx.x * blockDim.x + threadIdx.x;
    if (i < 4096) {
        double a = -2.0 * M_PI * (double)i / 8192.0;
        double s, c; sincos(a, &s, &c);
        g_tw8k[i] = make_float2((float)c, (float)s);
    }
    if (i < 8193) {
        double a = -2.0 * M_PI * (double)i / 16384.0;
        double s, c; sincos(a, &s, &c);
        g_u16[i] = make_float2((float)c, (float)s);
    }
}

/* ---------------- generic 32x32 tiled transpose: out[C][R] = in[R][C]^T ------- */
__global__ void transpose_kernel(const float* __restrict__ in, float* __restrict__ out,
                                 int R, int C) {
    __shared__ float t[32][33];
    int r0 = blockIdx.y * 32, c0 = blockIdx.x * 32;
    int x = threadIdx.x, y = threadIdx.y;
    for (int i = y; i < 32; i += 8)
        if (r0 + i < R && c0 + x < C) t[i][x] = in[(size_t)(r0 + i) * C + c0 + x];
    __syncthreads();
    for (int i = y; i < 32; i += 8)
        if (c0 + i < C && r0 + x < R) out[(size_t)(c0 + i) * R + r0 + x] = t[x][i];
}

/* ---------------- sactT[m][l] = silu(t[l]*W1[m] + b1[m]) ---------------- */
__global__ void sact_kernel(const float* __restrict__ t, const float* __restrict__ W1,
                            const float* __restrict__ b1) {
    int idx = blockIdx.x * blockDim.x + threadIdx.x;
    if (idx < 64 * LSEQ) {
        int m = idx >> 13, l = idx & (LSEQ - 1);
        float z = t[l] * W1[m] + b1[m];
        g_sactT[idx] = z / (1.0f + expf(-z));
    }
}

/* ---------------- h[d][l] = sum_m sactT[m][l]*W2[d][m] + b2[d] ---------------- */
__global__ void hmix_kernel(const float* __restrict__ W2, const float* __restrict__ b2) {
    __shared__ float s[64][129];
    int l0 = blockIdx.x * 128;
    int tid = threadIdx.x; /* 128 */
    for (int m = 0; m < 64; m++) s[m][tid] = g_sactT[m * LSEQ + l0 + tid];
    __syncthreads();
    for (int d0 = 0; d0 < 256; d0 += 4) {
        float a0 = b2[d0 + 0], a1 = b2[d0 + 1], a2 = b2[d0 + 2], a3 = b2[d0 + 3];
        #pragma unroll
        for (int m = 0; m < 64; m++) {
            float sv = s[m][tid];
            a0 += sv * __ldg(&W2[(d0 + 0) * 64 + m]);
            a1 += sv * __ldg(&W2[(d0 + 1) * 64 + m]);
            a2 += sv * __ldg(&W2[(d0 + 2) * 64 + m]);
            a3 += sv * __ldg(&W2[(d0 + 3) * 64 + m]);
        }
        g_h[(size_t)(d0 + 0) * LSEQ + l0 + tid] = a0;
        g_h[(size_t)(d0 + 1) * LSEQ + l0 + tid] = a1;
        g_h[(size_t)(d0 + 2) * LSEQ + l0 + tid] = a2;
        g_h[(size_t)(d0 + 3) * LSEQ + l0 + tid] = a3;
    }
}

/* ---------------- in-smem radix-2 FFT (8192-pt complex) ---------------- */
/* DIF forward: natural input -> bit-reversed output (position j holds bin brev13(j)) */
__device__ __forceinline__ void fft8k_dif(float2* zs, int tid) {
    for (int sh = 12; sh >= 0; sh--) {
        int s = 1 << sh;
        for (int j = tid; j < 4096; j += FFT_THREADS) {
            int off = j & (s - 1);
            int i0 = ((j >> sh) << (sh + 1)) + off;
            int i1 = i0 + s;
            float2 a = zs[i0], b = zs[i1];
            float2 w = g_tw8k[off << (12 - sh)];
            zs[i0] = make_float2(a.x + b.x, a.y + b.y);
            float2 d = make_float2(a.x - b.x, a.y - b.y);
            zs[i1] = make_float2(d.x * w.x - d.y * w.y, d.x * w.y + d.y * w.x);
        }
        __syncthreads();
    }
}
/* DIT inverse (conjugate twiddles): bit-reversed input -> natural output, unnormalized */
__device__ __forceinline__ void fft8k_dit_inv(float2* zs, int tid) {
    for (int sh = 0; sh <= 12; sh++) {
        int s = 1 << sh;
        for (int j = tid; j < 4096; j += FFT_THREADS) {
            int off = j & (s - 1);
            int i0 = ((j >> sh) << (sh + 1)) + off;
            int i1 = i0 + s;
            float2 w = g_tw8k[off << (12 - sh)];
            float2 a = zs[i0], b = zs[i1];
            float2 t = make_float2(b.x * w.x + b.y * w.y, b.y * w.x - b.x * w.y);
            zs[i0] = make_float2(a.x + t.x, a.y + t.y);
            zs[i1] = make_float2(a.x - t.x, a.y - t.y);
        }
        __syncthreads();
    }
}

__device__ __forceinline__ int brev13(int k) { return (int)(__brev((unsigned)k) >> 19); }

/* ---------------- filter FFT: Hf[d][k] = rfft16384(h[d] zero-padded), k=0..8192 --- */
__global__ void hf_kernel() {
    extern __shared__ float2 zs[];
    int d = blockIdx.x;
    int tid = threadIdx.x;
    const float2* hr = (const float2*)(g_h + (size_t)d * LSEQ);
    for (int n = tid; n < 4096; n += FFT_THREADS) zs[n] = hr[n];
    for (int n = 4096 + tid; n < NF; n += FFT_THREADS) zs[n] = make_float2(0.f, 0.f);
    __syncthreads();
    fft8k_dif(zs, tid);
    float2* Hf = g_Hf + (size_t)d * 8193;
    for (int k = tid; k <= 4096; k += FFT_THREADS) {
        if (k == 0) {
            float2 Z0 = zs[0];
            Hf[0]    = make_float2(Z0.x + Z0.y, 0.f);
            Hf[8192] = make_float2(Z0.x - Z0.y, 0.f);
        } else if (k == 4096) {
            float2 Z = zs[1]; /* brev13(4096)=1 */
            Hf[4096] = make_float2(Z.x, -Z.y); /* conj(Z) */
        } else {
            float2 Za = zs[brev13(k)], Zb = zs[brev13(8192 - k)];
            float2 Xe = make_float2(0.5f * (Za.x + Zb.x), 0.5f * (Za.y - Zb.y));
            float2 dd = make_float2(Za.x - Zb.x, Za.y + Zb.y);
            float2 Xo = make_float2(0.5f * dd.y, -0.5f * dd.x);
            float2 w  = g_u16[k];
            float2 wXo = cmul(w, Xo);
            Hf[k]        = make_float2(Xe.x + wXo.x, Xe.y + wXo.y);          /* X[k] */
            float2 Xm    = make_float2(Xe.x - wXo.x, Xe.y - wXo.y);
            Hf[8192 - k] = make_float2(Xm.x, -Xm.y);                        /* X[N-k]=conj(Xm) */
        }
    }
}

/* ------------- conv FFT: y[bd] = irfft16384( rfft16384(v[bd]) * Hf[d] )[:8192] ---- */
__global__ void conv_fft_kernel(const float* __restrict__ v, float* __restrict__ yout) {
    extern __shared__ float2 zs[];
    int bd = blockIdx.x;
    int d = bd & (DM - 1);
    int tid = threadIdx.x;
    const float2* vr = (const float2*)(v + (size_t)bd * LSEQ);
    for (int n = tid; n < 4096; n += FFT_THREADS) zs[n] = vr[n];
    for (int n = 4096 + tid; n < NF; n += FFT_THREADS) zs[n] = make_float2(0.f, 0.f);
    __syncthreads();
    fft8k_dif(zs, tid);
    const float2* Hf = g_Hf + (size_t)d * 8193;
    for (int k = tid; k <= 4096; k += FFT_THREADS) {
        if (k == 0) {
            float2 Z0 = zs[0];
            float X0 = Z0.x + Z0.y, XN = Z0.x - Z0.y;
            float2 H0 = Hf[0], HN = Hf[8192];
            float2 P0 = make_float2(X0 * H0.x, X0 * H0.y);
            float2 PN = make_float2(XN * HN.x, XN * HN.y);
            float2 Xe2 = make_float2(0.5f * (P0.x + PN.x), 0.5f * (P0.y - PN.y));
            float2 Xo2 = make_float2(0.5f * (P0.x - PN.x), 0.5f * (P0.y + PN.y));
            zs[0] = make_float2(Xe2.x - Xo2.y, Xe2.y + Xo2.x);
        } else if (k == 4096) {
            float2 Z = zs[1];
            float2 H = Hf[4096];
            /* Z' = Z * conj(H) */
            zs[1] = make_float2(Z.x * H.x + Z.y * H.y, Z.y * H.x - Z.x * H.y);
        } else {
            int p1 = brev13(k), p2 = brev13(8192 - k);
            float2 Za = zs[p1], Zb = zs[p2];
            float2 Xe = make_float2(0.5f * (Za.x + Zb.x), 0.5f * (Za.y - Zb.y));
            float2 dd = make_float2(Za.x - Zb.x, Za.y + Zb.y);
            float2 Xo = make_float2(0.5f * dd.y, -0.5f * dd.x);
            float2 w  = g_u16[k];
            float2 wXo = cmul(w, Xo);
            float2 Xp = make_float2(Xe.x + wXo.x, Xe.y + wXo.y);   /* X[k]          */
            float2 Xm = make_float2(Xe.x - wXo.x, Xe.y - wXo.y);   /* conj(X[N-k])  */
            float2 Hk = Hf[k], Hn = Hf[8192 - k];
            float2 P1 = cmul(Xp, Hk);                              /* P[k]          */
            float2 Q  = cmul(Xm, make_float2(Hn.x, -Hn.y));        /* conj(P[N-k])  */
            float2 Xe2 = make_float2(0.5f * (P1.x + Q.x), 0.5f * (P1.y + Q.y));
            float2 pmq = make_float2(P1.x - Q.x, P1.y - Q.y);
            float2 Xo2 = cmul(make_float2(w.x, -w.y), pmq);
            Xo2.x *= 0.5f; Xo2.y *= 0.5f;
            zs[p1] = make_float2(Xe2.x - Xo2.y, Xe2.y + Xo2.x);
            zs[p2] = make_float2(Xe2.x + Xo2.y, Xo2.x - Xe2.y);
        }
    }
    __syncthreads();
    fft8k_dit_inv(zs, tid);
    float2* yr = (float2*)(yout + (size_t)bd * LSEQ);
    const float sc = 1.0f / (float)NF;
    for (int n = tid; n < 4096; n += FFT_THREADS) {
        float2 t = zs[n];
        yr[n] = make_float2(t.x * sc, t.y * sc);
    }
}

/* ---------------- SIMT fp32 GEMM: C[M][N] = A[M][K] * B[K][N] + bias[N] -------- */
/* BM=128 BN=64 BK=32, 256 threads, 8x4 microtile. M%128==0, N%64==0, K%32==0.    */
__global__ void gemm_kernel(const float* __restrict__ A, const float* __restrict__ Bm,
                            const float* __restrict__ bias, float* __restrict__ C,
                            int M, int N, int K) {
    __shared__ float As[32][129]; /* [k][m], padded: conflict-free scalar access */
    __shared__ float Bs[32][64];
    int m0 = blockIdx.x * 128, n0 = blockIdx.y * 64;
    int tid = threadIdx.x;
    int tm = tid >> 4;   /* 0..15 -> m = tm*8 + mm  */
    int tn = tid & 15;   /* 0..15 -> n = tn*4 + nn  */
    float acc[8][4];
    #pragma unroll
    for (int i = 0; i < 8; i++)
        #pragma unroll
        for (int j = 0; j < 4; j++) acc[i][j] = 0.f;

    for (int k0 = 0; k0 < K; k0 += 32) {
        #pragma unroll
        for (int i = 0; i < 4; i++) {
            int idx = tid + i * 256;
            int m = idx >> 3, kg = idx & 7;
            float4 a4 = *(const float4*)&A[(size_t)(m0 + m) * K + k0 + kg * 4];
            As[kg * 4 + 0][m] = a4.x;
            As[kg * 4 + 1][m] = a4.y;
            As[kg * 4 + 2][m] = a4.z;
            As[kg * 4 + 3][m] = a4.w;
        }
        #pragma unroll
        for (int i = 0; i < 2; i++) {
            int idx = tid + i * 256;
            int kk = idx >> 4, ng = idx & 15;
            *(float4*)&Bs[kk][ng * 4] = *(const float4*)&Bm[(size_t)(k0 + kk) * N + n0 + ng * 4];
        }
        __syncthreads();
        #pragma unroll
        for (int kk = 0; kk < 32; kk++) {
            float a[8];
            #pragma unroll
            for (int mm = 0; mm < 8; mm++) a[mm] = As[kk][tm * 8 + mm];
            float4 b4 = *(const float4*)&Bs[kk][tn * 4];
            float b[4] = {b4.x, b4.y, b4.z, b4.w};
            #pragma unroll
            for (int mm = 0; mm < 8; mm++)
                #pragma unroll
                for (int nn = 0; nn < 4; nn++) acc[mm][nn] += a[mm] * b[nn];
        }
        __syncthreads();
    }
    float4 bb = *(const float4*)&bias[n0 + tn * 4];
    #pragma unroll
    for (int mm = 0; mm < 8; mm++) {
        int row = m0 + tm * 8 + mm;
        float4 r = make_float4(acc[mm][0] + bb.x, acc[mm][1] + bb.y,
                               acc[mm][2] + bb.z, acc[mm][3] + bb.w);
        *(float4*)&C[(size_t)row * N + n0 + tn * 4] = r;
    }
}

/* -------- split proj[b][l][c] (c<768) into v/g0/g1 as [b][c%256][l] (transposed) -- */
__global__ void split_transpose_kernel(const float* __restrict__ proj,
                                       float* __restrict__ v, float* __restrict__ g0,
                                       float* __restrict__ g1) {
    __shared__ float t[32][33];
    int b = blockIdx.z;
    int l0 = blockIdx.y * 32;
    int c0 = blockIdx.x * 32;
    int x = threadIdx.x, y = threadIdx.y;
    const float* p = proj + ((size_t)b * LSEQ + l0) * 768 + c0;
    for (int i = y; i < 32; i += 8) t[i][x] = p[(size_t)i * 768 + x]; /* t[l][c] */
    __syncthreads();
    int branch = c0 >> 8;
    int cc0 = c0 & 255;
    float* out = (branch == 0) ? v : ((branch == 1) ? g0 : g1);
    out += ((size_t)b * DM + cc0) * LSEQ + l0;
    for (int i = y; i < 32; i += 8) out[(size_t)i * LSEQ + x] = t[x][i];
}

/* -------- gating: gated[b][l][d] = y[b][d][l] * dwconv(g0)[b][d][l] * dwconv(g1) -- */
__global__ void gate_kernel(const float* __restrict__ yv, const float* __restrict__ g0r,
                            const float* __restrict__ g1r,
                            const float* __restrict__ w0, const float* __restrict__ b0,
                            const float* __restrict__ w1, const float* __restrict__ b1,
                            float* __restrict__ gated) {
    __shared__ float s0[32][34];
    __shared__ float s1[32][34];
    __shared__ float sy[32][33];
    __shared__ float so[32][33]; /* [l][d] staging */
    int b = blockIdx.z;
    int d0 = blockIdx.y * 32;
    int l0 = blockIdx.x * 32;
    int x = threadIdx.x, y = threadIdx.y;
    size_t base = ((size_t)b * DM + d0) * LSEQ + l0;
    for (int i = y; i < 32; i += 8) {
        size_t row = base + (size_t)i * LSEQ;
        s0[i][x + 1] = g0r[row + x];
        s1[i][x + 1] = g1r[row + x];
        sy[i][x] = yv[row + x];
    }
    if (x == 0) {
        for (int i = y; i < 32; i += 8) {
            size_t row = base + (size_t)i * LSEQ;
            s0[i][0] = (l0 > 0) ? g0r[row - 1] : 0.f;
            s1[i][0] = (l0 > 0) ? g1r[row - 1] : 0.f;
        }
    }
    if (x == 31) {
        for (int i = y; i < 32; i += 8) {
            size_t row = base + (size_t)i * LSEQ;
            s0[i][33] = (l0 + 32 < LSEQ) ? g0r[row + 32] : 0.f;
            s1[i][33] = (l0 + 32 < LSEQ) ? g1r[row + 32] : 0.f;
        }
    }
    __syncthreads();
    for (int i = y; i < 32; i += 8) {
        int d = d0 + i;
        float c0v = w0[d * 3 + 0] * s0[i][x] + w0[d * 3 + 1] * s0[i][x + 1] +
                    w0[d * 3 + 2] * s0[i][x + 2] + b0[d];
        float c1v = w1[d * 3 + 0] * s1[i][x] + w1[d * 3 + 1] * s1[i][x + 1] +
                    w1[d * 3 + 2] * s1[i][x + 2] + b1[d];
        so[x][i] = sy[i][x] * c0v * c1v;
    }
    __syncthreads();
    float* out = gated + ((size_t)b * LSEQ + l0) * DM + d0;
    for (int i = y; i < 32; i += 8) out[(size_t)i * DM + x] = so[i][x];
}

/* ---------------- launch ---------------- */
extern "C" void kernel_launch(void* const* d_in, const int* in_sizes, int n_in,
                              void* d_out, int out_size) {
    const float* x       = (const float*)d_in[0];
    const float* in_W    = (const float*)d_in[1];
    const float* in_b    = (const float*)d_in[2];
    const float* conv0_W = (const float*)d_in[3];
    const float* conv0_b = (const float*)d_in[4];
    const float* conv1_W = (const float*)d_in[5];
    const float* conv1_b = (const float*)d_in[6];
    const float* mlp_W1  = (const float*)d_in[7];
    const float* mlp_b1  = (const float*)d_in[8];
    const float* mlp_W2  = (const float*)d_in[9];
    const float* mlp_b2  = (const float*)d_in[10];
    const float* out_W   = (const float*)d_in[11];
    const float* out_b   = (const float*)d_in[12];
    const float* t       = (const float*)d_in[13];
    float* out = (float*)d_out;

    cudaFuncSetAttribute(conv_fft_kernel, cudaFuncAttributeMaxDynamicSharedMemorySize, 65536);
    cudaFuncSetAttribute(hf_kernel,       cudaFuncAttributeMaxDynamicSharedMemorySize, 65536);

    float* pWt1   = nullptr; cudaGetSymbolAddress((void**)&pWt1,   g_Wt1);
    float* pWt2   = nullptr; cudaGetSymbolAddress((void**)&pWt2,   g_Wt2);
    float* pProj  = nullptr; cudaGetSymbolAddress((void**)&pProj,  g_proj);
    float* pV     = nullptr; cudaGetSymbolAddress((void**)&pV,     g_v);
    float* pG0    = nullptr; cudaGetSymbolAddress((void**)&pG0,    g_g0);
    float* pG1    = nullptr; cudaGetSymbolAddress((void**)&pG1,    g_g1);
    float* pYc    = nullptr; cudaGetSymbolAddress((void**)&pYc,    g_yc);
    float* pGated = nullptr; cudaGetSymbolAddress((void**)&pGated, g_gated);

    init_tables_kernel<<<(8193 + 255) / 256, 256>>>();
    transpose_kernel<<<dim3(8, 24), dim3(32, 8)>>>(in_W, pWt1, 768, 256);
    transpose_kernel<<<dim3(8, 8),  dim3(32, 8)>>>(out_W, pWt2, 256, 256);
    sact_kernel<<<(64 * LSEQ + 255) / 256, 256>>>(t, mlp_W1, mlp_b1);
    hmix_kernel<<<LSEQ / 128, 128>>>(mlp_W2, mlp_b2);
    hf_kernel<<<DM, FFT_THREADS, 65536>>>();

    gemm_kernel<<<dim3((BATCH * LSEQ) / 128, 768 / 64), 256>>>(x, pWt1, in_b, pProj,
                                                               BATCH * LSEQ, 768, 256);
    split_transpose_kernel<<<dim3(768 / 32, LSEQ / 32, BATCH), dim3(32, 8)>>>(pProj, pV, pG0, pG1);
    conv_fft_kernel<<<BATCH * DM, FFT_THREADS, 65536>>>(pV, pYc);
    gate_kernel<<<dim3(LSEQ / 32, DM / 32, BATCH), dim3(32, 8)>>>(
        pYc, pG0, pG1, conv0_W, conv0_b, conv1_W, conv1_b, pGated);
    gemm_kernel<<<dim3((BATCH * LSEQ) / 128, 256 / 64), 256>>>(pGated, pWt2, out_b, out,
                                                               BATCH * LSEQ, 256, 256);
    (void)in_sizes; (void)n_in; (void)out_size;
}

// round 5
// speedup vs baseline: 1.2921x; 1.2921x over previous
#include <cuda_runtime.h>
#include <cuda_bf16.h>
#include <math.h>
#include <stdint.h>

#define BATCH 8
#define DM    256
#define LSEQ  8192
#define NF    8192      /* complex FFT size (for 16384-point real FFT) */
#define FFT_THREADS 512
#define BKP   40        /* padded bf16 row stride in GEMM smem tiles */

/* ---------------- scratch (device globals; no allocation allowed) ---------------- */
__device__ float2 g_tw8k[4096];                 /* exp(-2pi i j/8192), j<4096   */
__device__ float2 g_u16[8193];                  /* exp(-2pi i k/16384), k<=8192 */
__device__ float  g_sactT[64 * LSEQ];           /* silu(t*W1+b1)^T [64][L]     */
__device__ float  g_h[DM * LSEQ];               /* implicit filter [D][L]      */
__device__ float2 g_Hf[DM * 8193];              /* rfft16384(filter) [D][8193] */
__device__ __nv_bfloat16 g_xhi[(size_t)BATCH * LSEQ * DM];
__device__ __nv_bfloat16 g_xlo[(size_t)BATCH * LSEQ * DM];
__device__ __nv_bfloat16 g_W1hi[768 * 256];
__device__ __nv_bfloat16 g_W1lo[768 * 256];
__device__ __nv_bfloat16 g_W2hi[256 * 256];
__device__ __nv_bfloat16 g_W2lo[256 * 256];
__device__ __nv_bfloat16 g_ghi[(size_t)BATCH * LSEQ * DM];
__device__ __nv_bfloat16 g_glo[(size_t)BATCH * LSEQ * DM];
__device__ float  g_v [(size_t)BATCH * DM * LSEQ];
__device__ float  g_g0[(size_t)BATCH * DM * LSEQ];
__device__ float  g_g1[(size_t)BATCH * DM * LSEQ];
__device__ float  g_yc[(size_t)BATCH * DM * LSEQ];

/* ---------------- helpers ---------------- */
__device__ __forceinline__ float2 cmul(float2 a, float2 b) {
    return make_float2(a.x * b.x - a.y * b.y, a.x * b.y + a.y * b.x);
}

/* ---------------- table init (idempotent, runs every launch) ---------------- */
__global__ void init_tables_kernel() {
    int i = blockIdx.x * blockDim.x + threadIdx.x;
    if (i < 4096) {
        double a = -2.0 * M_PI * (double)i / 8192.0;
        double s, c; sincos(a, &s, &c);
        g_tw8k[i] = make_float2((float)c, (float)s);
    }
    if (i < 8193) {
        double a = -2.0 * M_PI * (double)i / 16384.0;
        double s, c; sincos(a, &s, &c);
        g_u16[i] = make_float2((float)c, (float)s);
    }
}

/* ---------------- fp32 -> bf16 hi/lo split ---------------- */
__global__ void split_bf16_kernel(const float* __restrict__ in,
                                  __nv_bfloat16* __restrict__ hi,
                                  __nv_bfloat16* __restrict__ lo, int n) {
    int i = 4 * (blockIdx.x * blockDim.x + threadIdx.x);
    if (i < n) {
        float4 v = *(const float4*)&in[i];
        __nv_bfloat16 h0 = __float2bfloat16_rn(v.x);
        __nv_bfloat16 h1 = __float2bfloat16_rn(v.y);
        __nv_bfloat16 h2 = __float2bfloat16_rn(v.z);
        __nv_bfloat16 h3 = __float2bfloat16_rn(v.w);
        __nv_bfloat162 ph01; ph01.x = h0; ph01.y = h1;
        __nv_bfloat162 ph23; ph23.x = h2; ph23.y = h3;
        *(__nv_bfloat162*)&hi[i]     = ph01;
        *(__nv_bfloat162*)&hi[i + 2] = ph23;
        __nv_bfloat162 pl01, pl23;
        pl01.x = __float2bfloat16_rn(v.x - __bfloat162float(h0));
        pl01.y = __float2bfloat16_rn(v.y - __bfloat162float(h1));
        pl23.x = __float2bfloat16_rn(v.z - __bfloat162float(h2));
        pl23.y = __float2bfloat16_rn(v.w - __bfloat162float(h3));
        *(__nv_bfloat162*)&lo[i]     = pl01;
        *(__nv_bfloat162*)&lo[i + 2] = pl23;
    }
}

/* ---------------- sactT[m][l] = silu(t[l]*W1[m] + b1[m]) ---------------- */
__global__ void sact_kernel(const float* __restrict__ t, const float* __restrict__ W1,
                            const float* __restrict__ b1) {
    int idx = blockIdx.x * blockDim.x + threadIdx.x;
    if (idx < 64 * LSEQ) {
        int m = idx >> 13, l = idx & (LSEQ - 1);
        float z = t[l] * W1[m] + b1[m];
        g_sactT[idx] = z / (1.0f + expf(-z));
    }
}

/* ---------------- h[d][l] = sum_m sactT[m][l]*W2[d][m] + b2[d] ---------------- */
__global__ void hmix_kernel(const float* __restrict__ W2, const float* __restrict__ b2) {
    __shared__ float s[64][129];
    int l0 = blockIdx.x * 128;
    int tid = threadIdx.x; /* 128 */
    for (int m = 0; m < 64; m++) s[m][tid] = g_sactT[m * LSEQ + l0 + tid];
    __syncthreads();
    for (int d0 = 0; d0 < 256; d0 += 4) {
        float a0 = b2[d0 + 0], a1 = b2[d0 + 1], a2 = b2[d0 + 2], a3 = b2[d0 + 3];
        #pragma unroll
        for (int m = 0; m < 64; m++) {
            float sv = s[m][tid];
            a0 += sv * __ldg(&W2[(d0 + 0) * 64 + m]);
            a1 += sv * __ldg(&W2[(d0 + 1) * 64 + m]);
            a2 += sv * __ldg(&W2[(d0 + 2) * 64 + m]);
            a3 += sv * __ldg(&W2[(d0 + 3) * 64 + m]);
        }
        g_h[(size_t)(d0 + 0) * LSEQ + l0 + tid] = a0;
        g_h[(size_t)(d0 + 1) * LSEQ + l0 + tid] = a1;
        g_h[(size_t)(d0 + 2) * LSEQ + l0 + tid] = a2;
        g_h[(size_t)(d0 + 3) * LSEQ + l0 + tid] = a3;
    }
}

/* ---------------- in-smem radix-2 FFT (8192-pt complex) ---------------- */
__device__ __forceinline__ void fft8k_dif(float2* zs, int tid) {
    for (int sh = 12; sh >= 0; sh--) {
        int s = 1 << sh;
        for (int j = tid; j < 4096; j += FFT_THREADS) {
            int off = j & (s - 1);
            int i0 = ((j >> sh) << (sh + 1)) + off;
            int i1 = i0 + s;
            float2 a = zs[i0], b = zs[i1];
            float2 w = g_tw8k[off << (12 - sh)];
            zs[i0] = make_float2(a.x + b.x, a.y + b.y);
            float2 d = make_float2(a.x - b.x, a.y - b.y);
            zs[i1] = make_float2(d.x * w.x - d.y * w.y, d.x * w.y + d.y * w.x);
        }
        __syncthreads();
    }
}
__device__ __forceinline__ void fft8k_dit_inv(float2* zs, int tid) {
    for (int sh = 0; sh <= 12; sh++) {
        int s = 1 << sh;
        for (int j = tid; j < 4096; j += FFT_THREADS) {
            int off = j & (s - 1);
            int i0 = ((j >> sh) << (sh + 1)) + off;
            int i1 = i0 + s;
            float2 w = g_tw8k[off << (12 - sh)];
            float2 a = zs[i0], b = zs[i1];
            float2 t = make_float2(b.x * w.x + b.y * w.y, b.y * w.x - b.x * w.y);
            zs[i0] = make_float2(a.x + t.x, a.y + t.y);
            zs[i1] = make_float2(a.x - t.x, a.y - t.y);
        }
        __syncthreads();
    }
}

__device__ __forceinline__ int brev13(int k) { return (int)(__brev((unsigned)k) >> 19); }

/* ---------------- filter FFT ---------------- */
__global__ void hf_kernel() {
    extern __shared__ float2 zs[];
    int d = blockIdx.x;
    int tid = threadIdx.x;
    const float2* hr = (const float2*)(g_h + (size_t)d * LSEQ);
    for (int n = tid; n < 4096; n += FFT_THREADS) zs[n] = hr[n];
    for (int n = 4096 + tid; n < NF; n += FFT_THREADS) zs[n] = make_float2(0.f, 0.f);
    __syncthreads();
    fft8k_dif(zs, tid);
    float2* Hf = g_Hf + (size_t)d * 8193;
    for (int k = tid; k <= 4096; k += FFT_THREADS) {
        if (k == 0) {
            float2 Z0 = zs[0];
            Hf[0]    = make_float2(Z0.x + Z0.y, 0.f);
            Hf[8192] = make_float2(Z0.x - Z0.y, 0.f);
        } else if (k == 4096) {
            float2 Z = zs[1];
            Hf[4096] = make_float2(Z.x, -Z.y);
        } else {
            float2 Za = zs[brev13(k)], Zb = zs[brev13(8192 - k)];
            float2 Xe = make_float2(0.5f * (Za.x + Zb.x), 0.5f * (Za.y - Zb.y));
            float2 dd = make_float2(Za.x - Zb.x, Za.y + Zb.y);
            float2 Xo = make_float2(0.5f * dd.y, -0.5f * dd.x);
            float2 w  = g_u16[k];
            float2 wXo = cmul(w, Xo);
            Hf[k]        = make_float2(Xe.x + wXo.x, Xe.y + wXo.y);
            float2 Xm    = make_float2(Xe.x - wXo.x, Xe.y - wXo.y);
            Hf[8192 - k] = make_float2(Xm.x, -Xm.y);
        }
    }
}

/* ------------- conv FFT ---- */
__global__ void conv_fft_kernel(const float* __restrict__ v, float* __restrict__ yout) {
    extern __shared__ float2 zs[];
    int bd = blockIdx.x;
    int d = bd & (DM - 1);
    int tid = threadIdx.x;
    const float2* vr = (const float2*)(v + (size_t)bd * LSEQ);
    for (int n = tid; n < 4096; n += FFT_THREADS) zs[n] = vr[n];
    for (int n = 4096 + tid; n < NF; n += FFT_THREADS) zs[n] = make_float2(0.f, 0.f);
    __syncthreads();
    fft8k_dif(zs, tid);
    const float2* Hf = g_Hf + (size_t)d * 8193;
    for (int k = tid; k <= 4096; k += FFT_THREADS) {
        if (k == 0) {
            float2 Z0 = zs[0];
            float X0 = Z0.x + Z0.y, XN = Z0.x - Z0.y;
            float2 H0 = Hf[0], HN = Hf[8192];
            float2 P0 = make_float2(X0 * H0.x, X0 * H0.y);
            float2 PN = make_float2(XN * HN.x, XN * HN.y);
            float2 Xe2 = make_float2(0.5f * (P0.x + PN.x), 0.5f * (P0.y - PN.y));
            float2 Xo2 = make_float2(0.5f * (P0.x - PN.x), 0.5f * (P0.y + PN.y));
            zs[0] = make_float2(Xe2.x - Xo2.y, Xe2.y + Xo2.x);
        } else if (k == 4096) {
            float2 Z = zs[1];
            float2 H = Hf[4096];
            zs[1] = make_float2(Z.x * H.x + Z.y * H.y, Z.y * H.x - Z.x * H.y);
        } else {
            int p1 = brev13(k), p2 = brev13(8192 - k);
            float2 Za = zs[p1], Zb = zs[p2];
            float2 Xe = make_float2(0.5f * (Za.x + Zb.x), 0.5f * (Za.y - Zb.y));
            float2 dd = make_float2(Za.x - Zb.x, Za.y + Zb.y);
            float2 Xo = make_float2(0.5f * dd.y, -0.5f * dd.x);
            float2 w  = g_u16[k];
            float2 wXo = cmul(w, Xo);
            float2 Xp = make_float2(Xe.x + wXo.x, Xe.y + wXo.y);
            float2 Xm = make_float2(Xe.x - wXo.x, Xe.y - wXo.y);
            float2 Hk = Hf[k], Hn = Hf[8192 - k];
            float2 P1 = cmul(Xp, Hk);
            float2 Q  = cmul(Xm, make_float2(Hn.x, -Hn.y));
            float2 Xe2 = make_float2(0.5f * (P1.x + Q.x), 0.5f * (P1.y + Q.y));
            float2 pmq = make_float2(P1.x - Q.x, P1.y - Q.y);
            float2 Xo2 = cmul(make_float2(w.x, -w.y), pmq);
            Xo2.x *= 0.5f; Xo2.y *= 0.5f;
            zs[p1] = make_float2(Xe2.x - Xo2.y, Xe2.y + Xo2.x);
            zs[p2] = make_float2(Xe2.x + Xo2.y, Xo2.x - Xe2.y);
        }
    }
    __syncthreads();
    fft8k_dit_inv(zs, tid);
    float2* yr = (float2*)(yout + (size_t)bd * LSEQ);
    const float sc = 1.0f / (float)NF;
    for (int n = tid; n < 4096; n += FFT_THREADS) {
        float2 t = zs[n];
        yr[n] = make_float2(t.x * sc, t.y * sc);
    }
}

/* ---------------- bf16 split-precision tensor-core GEMM ------------------------ */
/* C[M][N] = A[M][K] @ W[N][K]^T + bias, A = Ahi+Alo, W = Bhi+Blo (bf16 splits).  */
/* 128x128 CTA tile, BK=32, 8 warps (4x2), warp tile 32x64, mma.m16n8k16.        */
/* EPI=0: write C row-major [M][N].                                               */
/* EPI=1: write transposed into per-branch [b][d][l] buffers (v/g0/g1).          */
__device__ __forceinline__ void mma_bf16(float c[4], const unsigned a[4],
                                         unsigned b0, unsigned b1) {
    asm volatile(
        "mma.sync.aligned.m16n8k16.row.col.f32.bf16.bf16.f32 "
        "{%0,%1,%2,%3}, {%4,%5,%6,%7}, {%8,%9}, {%0,%1,%2,%3};\n"
        : "+f"(c[0]), "+f"(c[1]), "+f"(c[2]), "+f"(c[3])
        : "r"(a[0]), "r"(a[1]), "r"(a[2]), "r"(a[3]), "r"(b0), "r"(b1));
}

template <int EPI>
__global__ void __launch_bounds__(256) mma_gemm_kernel(
    const __nv_bfloat16* __restrict__ Ahi, const __nv_bfloat16* __restrict__ Alo,
    const __nv_bfloat16* __restrict__ Bhi, const __nv_bfloat16* __restrict__ Blo,
    const float* __restrict__ bias,
    float* __restrict__ C0p, float* __restrict__ C1p, float* __restrict__ C2p,
    int M, int N, int K) {
    extern __shared__ char smraw[];
    __nv_bfloat16* sAhi = (__nv_bfloat16*)smraw;            /* [128][BKP] */
    __nv_bfloat16* sAlo = sAhi + 128 * BKP;
    __nv_bfloat16* sBhi = sAlo + 128 * BKP;
    __nv_bfloat16* sBlo = sBhi + 128 * BKP;
    float* ep = (float*)smraw;                              /* [128][132] staging */

    int tid = threadIdx.x;
    int warp = tid >> 5, lane = tid & 31;
    int gid = lane >> 2, tig = lane & 3;
    int warp_m = (warp >> 1) * 32;   /* 0,32,64,96 */
    int warp_n = (warp & 1) * 64;    /* 0,64       */
    int m0 = blockIdx.y * 128, n0 = blockIdx.x * 128;
    int ldv = K >> 3;                /* uint4 per row */

    float acc[2][8][4];
    #pragma unroll
    for (int mt = 0; mt < 2; mt++)
        #pragma unroll
        for (int nt = 0; nt < 8; nt++)
            #pragma unroll
            for (int q = 0; q < 4; q++) acc[mt][nt][q] = 0.f;

    for (int k0 = 0; k0 < K; k0 += 32) {
        __syncthreads();
        /* stage tiles: 128 rows x 32 k (bf16) each, coalesced uint4 */
        {
            const uint4* gAh = (const uint4*)Ahi;
            const uint4* gAl = (const uint4*)Alo;
            const uint4* gBh = (const uint4*)Bhi;
            const uint4* gBl = (const uint4*)Blo;
            int kq4 = k0 >> 3;
            #pragma unroll
            for (int i = tid; i < 512; i += 256) {
                int row = i >> 2, kq = i & 3;
                *(uint4*)&sAhi[row * BKP + kq * 8] = gAh[(size_t)(m0 + row) * ldv + kq4 + kq];
                *(uint4*)&sAlo[row * BKP + kq * 8] = gAl[(size_t)(m0 + row) * ldv + kq4 + kq];
                *(uint4*)&sBhi[row * BKP + kq * 8] = gBh[(size_t)(n0 + row) * ldv + kq4 + kq];
                *(uint4*)&sBlo[row * BKP + kq * 8] = gBl[(size_t)(n0 + row) * ldv + kq4 + kq];
            }
        }
        __syncthreads();
        #pragma unroll
        for (int k16 = 0; k16 < 32; k16 += 16) {
            unsigned ah[2][4], al[2][4];
            #pragma unroll
            for (int mt = 0; mt < 2; mt++) {
                int base = (warp_m + mt * 16 + gid) * BKP + k16 + 2 * tig;
                ah[mt][0] = *(const unsigned*)&sAhi[base];
                ah[mt][1] = *(const unsigned*)&sAhi[base + 8 * BKP];
                ah[mt][2] = *(const unsigned*)&sAhi[base + 8];
                ah[mt][3] = *(const unsigned*)&sAhi[base + 8 * BKP + 8];
                al[mt][0] = *(const unsigned*)&sAlo[base];
                al[mt][1] = *(const unsigned*)&sAlo[base + 8 * BKP];
                al[mt][2] = *(const unsigned*)&sAlo[base + 8];
                al[mt][3] = *(const unsigned*)&sAlo[base + 8 * BKP + 8];
            }
            #pragma unroll
            for (int nt = 0; nt < 8; nt++) {
                int cbase = (warp_n + nt * 8 + gid) * BKP + k16 + 2 * tig;
                unsigned bh0 = *(const unsigned*)&sBhi[cbase];
                unsigned bh1 = *(const unsigned*)&sBhi[cbase + 8];
                unsigned bl0 = *(const unsigned*)&sBlo[cbase];
                unsigned bl1 = *(const unsigned*)&sBlo[cbase + 8];
                #pragma unroll
                for (int mt = 0; mt < 2; mt++) {
                    mma_bf16(acc[mt][nt], ah[mt], bh0, bh1);
                    mma_bf16(acc[mt][nt], ah[mt], bl0, bl1);
                    mma_bf16(acc[mt][nt], al[mt], bh0, bh1);
                }
            }
        }
    }

    if (EPI == 0) {
        /* row-major C with bias */
        #pragma unroll
        for (int mt = 0; mt < 2; mt++) {
            #pragma unroll
            for (int nt = 0; nt < 8; nt++) {
                int r = m0 + warp_m + mt * 16 + gid;
                int c = n0 + warp_n + nt * 8 + 2 * tig;
                float b0v = bias[c], b1v = bias[c + 1];
                float2 w0 = make_float2(acc[mt][nt][0] + b0v, acc[mt][nt][1] + b1v);
                float2 w1 = make_float2(acc[mt][nt][2] + b0v, acc[mt][nt][3] + b1v);
                *(float2*)&C0p[(size_t)r * N + c] = w0;
                *(float2*)&C0p[(size_t)(r + 8) * N + c] = w1;
            }
        }
    } else {
        /* transposed epilogue -> v/g0/g1 in [b][d][l] layout, bias folded in */
        __syncthreads();
        #pragma unroll
        for (int mt = 0; mt < 2; mt++) {
            #pragma unroll
            for (int nt = 0; nt < 8; nt++) {
                int rl = warp_m + mt * 16 + gid;
                int cl = warp_n + nt * 8 + 2 * tig;
                ep[(size_t)cl * 132 + rl]           = acc[mt][nt][0];
                ep[(size_t)(cl + 1) * 132 + rl]     = acc[mt][nt][1];
                ep[(size_t)cl * 132 + rl + 8]       = acc[mt][nt][2];
                ep[(size_t)(cl + 1) * 132 + rl + 8] = acc[mt][nt][3];
            }
        }
        __syncthreads();
        int b = m0 >> 13;
        int l0 = m0 & (LSEQ - 1);
        int branch = n0 >> 8;
        int cc0 = n0 & 255;
        float* out = (branch == 0) ? C0p : ((branch == 1) ? C1p : C2p);
        for (int i = tid; i < 16384; i += 256) {
            int c = i >> 7, l = i & 127;
            out[((size_t)b * DM + cc0 + c) * LSEQ + l0 + l] = ep[c * 132 + l] + bias[n0 + c];
        }
    }
}

/* -------- gating -> bf16 hi/lo in [b][l][d] (feeds out-proj GEMM directly) ----- */
__global__ void gate_kernel(const float* __restrict__ yv, const float* __restrict__ g0r,
                            const float* __restrict__ g1r,
                            const float* __restrict__ w0, const float* __restrict__ b0,
                            const float* __restrict__ w1, const float* __restrict__ b1,
                            __nv_bfloat16* __restrict__ ohi, __nv_bfloat16* __restrict__ olo) {
    __shared__ float s0[32][34];
    __shared__ float s1[32][34];
    __shared__ float sy[32][33];
    __shared__ float so[32][33]; /* [l][d] staging */
    int b = blockIdx.z;
    int d0 = blockIdx.y * 32;
    int l0 = blockIdx.x * 32;
    int x = threadIdx.x, y = threadIdx.y;
    size_t base = ((size_t)b * DM + d0) * LSEQ + l0;
    for (int i = y; i < 32; i += 8) {
        size_t row = base + (size_t)i * LSEQ;
        s0[i][x + 1] = g0r[row + x];
        s1[i][x + 1] = g1r[row + x];
        sy[i][x] = yv[row + x];
    }
    if (x == 0) {
        for (int i = y; i < 32; i += 8) {
            size_t row = base + (size_t)i * LSEQ;
            s0[i][0] = (l0 > 0) ? g0r[row - 1] : 0.f;
            s1[i][0] = (l0 > 0) ? g1r[row - 1] : 0.f;
        }
    }
    if (x == 31) {
        for (int i = y; i < 32; i += 8) {
            size_t row = base + (size_t)i * LSEQ;
            s0[i][33] = (l0 + 32 < LSEQ) ? g0r[row + 32] : 0.f;
            s1[i][33] = (l0 + 32 < LSEQ) ? g1r[row + 32] : 0.f;
        }
    }
    __syncthreads();
    for (int i = y; i < 32; i += 8) {
        int d = d0 + i;
        float c0v = w0[d * 3 + 0] * s0[i][x] + w0[d * 3 + 1] * s0[i][x + 1] +
                    w0[d * 3 + 2] * s0[i][x + 2] + b0[d];
        float c1v = w1[d * 3 + 0] * s1[i][x] + w1[d * 3 + 1] * s1[i][x + 1] +
                    w1[d * 3 + 2] * s1[i][x + 2] + b1[d];
        so[x][i] = sy[i][x] * c0v * c1v;
    }
    __syncthreads();
    size_t ob = ((size_t)b * LSEQ + l0) * DM + d0;
    for (int i = y; i < 32; i += 8) {
        float vv = so[i][x];
        __nv_bfloat16 h = __float2bfloat16_rn(vv);
        ohi[ob + (size_t)i * DM + x] = h;
        olo[ob + (size_t)i * DM + x] = __float2bfloat16_rn(vv - __bfloat162float(h));
    }
}

/* ---------------- launch ---------------- */
extern "C" void kernel_launch(void* const* d_in, const int* in_sizes, int n_in,
                              void* d_out, int out_size) {
    const float* x       = (const float*)d_in[0];
    const float* in_W    = (const float*)d_in[1];
    const float* in_b    = (const float*)d_in[2];
    const float* conv0_W = (const float*)d_in[3];
    const float* conv0_b = (const float*)d_in[4];
    const float* conv1_W = (const float*)d_in[5];
    const float* conv1_b = (const float*)d_in[6];
    const float* mlp_W1  = (const float*)d_in[7];
    const float* mlp_b1  = (const float*)d_in[8];
    const float* mlp_W2  = (const float*)d_in[9];
    const float* mlp_b2  = (const float*)d_in[10];
    const float* out_W   = (const float*)d_in[11];
    const float* out_b   = (const float*)d_in[12];
    const float* t       = (const float*)d_in[13];
    float* out = (float*)d_out;

    cudaFuncSetAttribute(conv_fft_kernel, cudaFuncAttributeMaxDynamicSharedMemorySize, 65536);
    cudaFuncSetAttribute(hf_kernel,       cudaFuncAttributeMaxDynamicSharedMemorySize, 65536);
    cudaFuncSetAttribute(mma_gemm_kernel<1>, cudaFuncAttributeMaxDynamicSharedMemorySize, 128 * 132 * 4);
    cudaFuncSetAttribute(mma_gemm_kernel<0>, cudaFuncAttributeMaxDynamicSharedMemorySize, 4 * 128 * BKP * 2);

    __nv_bfloat16 *pXhi, *pXlo, *pW1hi, *pW1lo, *pW2hi, *pW2lo, *pGhi, *pGlo;
    cudaGetSymbolAddress((void**)&pXhi,  g_xhi);
    cudaGetSymbolAddress((void**)&pXlo,  g_xlo);
    cudaGetSymbolAddress((void**)&pW1hi, g_W1hi);
    cudaGetSymbolAddress((void**)&pW1lo, g_W1lo);
    cudaGetSymbolAddress((void**)&pW2hi, g_W2hi);
    cudaGetSymbolAddress((void**)&pW2lo, g_W2lo);
    cudaGetSymbolAddress((void**)&pGhi,  g_ghi);
    cudaGetSymbolAddress((void**)&pGlo,  g_glo);
    float *pV, *pG0, *pG1, *pYc;
    cudaGetSymbolAddress((void**)&pV,  g_v);
    cudaGetSymbolAddress((void**)&pG0, g_g0);
    cudaGetSymbolAddress((void**)&pG1, g_g1);
    cudaGetSymbolAddress((void**)&pYc, g_yc);

    const int M = BATCH * LSEQ;

    init_tables_kernel<<<(8193 + 255) / 256, 256>>>();
    split_bf16_kernel<<<(M * DM / 4 + 255) / 256, 256>>>(x, pXhi, pXlo, M * DM);
    split_bf16_kernel<<<(768 * 256 / 4 + 255) / 256, 256>>>(in_W, pW1hi, pW1lo, 768 * 256);
    split_bf16_kernel<<<(256 * 256 / 4 + 255) / 256, 256>>>(out_W, pW2hi, pW2lo, 256 * 256);
    sact_kernel<<<(64 * LSEQ + 255) / 256, 256>>>(t, mlp_W1, mlp_b1);
    hmix_kernel<<<LSEQ / 128, 128>>>(mlp_W2, mlp_b2);
    hf_kernel<<<DM, FFT_THREADS, 65536>>>();

    /* in-proj: [M,768] via bf16-split mma; epilogue writes v/g0/g1 transposed */
    mma_gemm_kernel<1><<<dim3(768 / 128, M / 128), 256, 128 * 132 * 4>>>(
        pXhi, pXlo, pW1hi, pW1lo, in_b, pV, pG0, pG1, M, 768, 256);

    conv_fft_kernel<<<BATCH * DM, FFT_THREADS, 65536>>>(pV, pYc);
    gate_kernel<<<dim3(LSEQ / 32, DM / 32, BATCH), dim3(32, 8)>>>(
        pYc, pG0, pG1, conv0_W, conv0_b, conv1_W, conv1_b, pGhi, pGlo);

    /* out-proj: [M,256] */
    mma_gemm_kernel<0><<<dim3(256 / 128, M / 128), 256, 4 * 128 * BKP * 2>>>(
        pGhi, pGlo, pW2hi, pW2lo, out_b, out, nullptr, nullptr, M, 256, 256);

    (void)in_sizes; (void)n_in; (void)out_size;
}

// round 8
// speedup vs baseline: 1.7935x; 1.3881x over previous
#include <cuda_runtime.h>
#include <cuda_bf16.h>
#include <math.h>
#include <stdint.h>

#define BATCH 8
#define DM    256
#define LSEQ  8192
#define NF    8192      /* complex FFT size (for 16384-point real FFT) */
#define FFT_THREADS 512
#define BKP   40        /* padded bf16 row stride in GEMM smem tiles */

/* ---------------- scratch (device globals; no allocation allowed) ---------------- */
__device__ float2 g_tw8k[4096];                 /* exp(-2pi i j/8192), j<4096   */
__device__ float2 g_u16[8193];                  /* exp(-2pi i k/16384), k<=8192 */
__device__ float  g_sactT[64 * LSEQ];           /* silu(t*W1+b1)^T [64][L]     */
__device__ float  g_h[DM * LSEQ];               /* implicit filter [D][L]      */
__device__ float2 g_Hf[DM * 8193];              /* rfft16384(filter) [D][8193] */
__device__ __nv_bfloat16 g_W1hi[768 * 256];
__device__ __nv_bfloat16 g_W1lo[768 * 256];
__device__ __nv_bfloat16 g_W2hi[256 * 256];
__device__ __nv_bfloat16 g_W2lo[256 * 256];
__device__ float  g_v [(size_t)BATCH * DM * LSEQ];
__device__ float  g_g0[(size_t)BATCH * DM * LSEQ];
__device__ float  g_g1[(size_t)BATCH * DM * LSEQ];
__device__ float  g_yc[(size_t)BATCH * DM * LSEQ];
__device__ float  g_gated[(size_t)BATCH * LSEQ * DM];

/* ---------------- helpers ---------------- */
__device__ __forceinline__ float2 cmul(float2 a, float2 b) {
    return make_float2(a.x * b.x - a.y * b.y, a.x * b.y + a.y * b.x);
}
__device__ __forceinline__ float2 cmulc(float2 a, float2 w) { /* a * conj(w) */
    return make_float2(a.x * w.x + a.y * w.y, a.y * w.x - a.x * w.y);
}
/* storage position of frequency bin k after radix-4(x6)+radix-2 DIF */
__device__ __forceinline__ int perm13(int k) {
    unsigned v = __brev((unsigned)k) >> 19;
    unsigned w = v >> 1;
    unsigned r = ((w & 0xAAAu) >> 1) | ((w & 0x555u) << 1);
    return (int)((r << 1) | (v & 1u));
}

/* ---------------- table init (idempotent, runs every launch) ---------------- */
__global__ void init_tables_kernel() {
    int i = blockIdx.x * blockDim.x + threadIdx.x;
    if (i < 4096) {
        double a = -2.0 * M_PI * (double)i / 8192.0;
        double s, c; sincos(a, &s, &c);
        g_tw8k[i] = make_float2((float)c, (float)s);
    }
    if (i < 8193) {
        double a = -2.0 * M_PI * (double)i / 16384.0;
        double s, c; sincos(a, &s, &c);
        g_u16[i] = make_float2((float)c, (float)s);
    }
}

/* ---------------- fp32 -> bf16 hi/lo split (weights only) ---------------- */
__global__ void split_bf16_kernel(const float* __restrict__ in,
                                  __nv_bfloat16* __restrict__ hi,
                                  __nv_bfloat16* __restrict__ lo, int n) {
    int i = 4 * (blockIdx.x * blockDim.x + threadIdx.x);
    if (i < n) {
        float4 v = *(const float4*)&in[i];
        __nv_bfloat16 h0 = __float2bfloat16_rn(v.x);
        __nv_bfloat16 h1 = __float2bfloat16_rn(v.y);
        __nv_bfloat16 h2 = __float2bfloat16_rn(v.z);
        __nv_bfloat16 h3 = __float2bfloat16_rn(v.w);
        __nv_bfloat162 ph01; ph01.x = h0; ph01.y = h1;
        __nv_bfloat162 ph23; ph23.x = h2; ph23.y = h3;
        *(__nv_bfloat162*)&hi[i]     = ph01;
        *(__nv_bfloat162*)&hi[i + 2] = ph23;
        __nv_bfloat162 pl01, pl23;
        pl01.x = __float2bfloat16_rn(v.x - __bfloat162float(h0));
        pl01.y = __float2bfloat16_rn(v.y - __bfloat162float(h1));
        pl23.x = __float2bfloat16_rn(v.z - __bfloat162float(h2));
        pl23.y = __float2bfloat16_rn(v.w - __bfloat162float(h3));
        *(__nv_bfloat162*)&lo[i]     = pl01;
        *(__nv_bfloat162*)&lo[i + 2] = pl23;
    }
}

/* ---------------- sactT[m][l] = silu(t[l]*W1[m] + b1[m]) ---------------- */
__global__ void sact_kernel(const float* __restrict__ t, const float* __restrict__ W1,
                            const float* __restrict__ b1) {
    int idx = blockIdx.x * blockDim.x + threadIdx.x;
    if (idx < 64 * LSEQ) {
        int m = idx >> 13, l = idx & (LSEQ - 1);
        float z = t[l] * W1[m] + b1[m];
        g_sactT[idx] = z / (1.0f + expf(-z));
    }
}

/* ---------------- h[d][l] = sum_m sactT[m][l]*W2[d][m] + b2[d] ---------------- */
__global__ void hmix_kernel(const float* __restrict__ W2, const float* __restrict__ b2) {
    __shared__ float s[64][129];
    int l0 = blockIdx.x * 128;
    int tid = threadIdx.x; /* 128 */
    for (int m = 0; m < 64; m++) s[m][tid] = g_sactT[m * LSEQ + l0 + tid];
    __syncthreads();
    for (int d0 = 0; d0 < 256; d0 += 4) {
        float a0 = b2[d0 + 0], a1 = b2[d0 + 1], a2 = b2[d0 + 2], a3 = b2[d0 + 3];
        #pragma unroll
        for (int m = 0; m < 64; m++) {
            float sv = s[m][tid];
            a0 += sv * __ldg(&W2[(d0 + 0) * 64 + m]);
            a1 += sv * __ldg(&W2[(d0 + 1) * 64 + m]);
            a2 += sv * __ldg(&W2[(d0 + 2) * 64 + m]);
            a3 += sv * __ldg(&W2[(d0 + 3) * 64 + m]);
        }
        g_h[(size_t)(d0 + 0) * LSEQ + l0 + tid] = a0;
        g_h[(size_t)(d0 + 1) * LSEQ + l0 + tid] = a1;
        g_h[(size_t)(d0 + 2) * LSEQ + l0 + tid] = a2;
        g_h[(size_t)(d0 + 3) * LSEQ + l0 + tid] = a3;
    }
}

/* -------------- in-smem radix-4 FFT (8192-pt complex), 6xR4 + 1xR2 -------------- */
/* forward DIF: natural input -> digit-permuted output (bin k at perm13(k))        */
__device__ __forceinline__ void fft8k_r4_dif(float2* zs, int tid) {
    #pragma unroll
    for (int ls = 11; ls >= 1; ls -= 2) {
        int s = 1 << ls;
        for (int j = tid; j < 2048; j += FFT_THREADS) {
            int o = j & (s - 1);
            int base = ((j >> ls) << (ls + 2)) + o;
            float2 a = zs[base], b = zs[base + s], c = zs[base + 2 * s], d = zs[base + 3 * s];
            float2 t0 = make_float2(a.x + c.x, a.y + c.y);
            float2 t1 = make_float2(a.x - c.x, a.y - c.y);
            float2 t2 = make_float2(b.x + d.x, b.y + d.y);
            float2 t3 = make_float2(b.y - d.y, -(b.x - d.x));   /* -i(b-d) */
            int twi = o << (11 - ls);
            float2 w1 = g_tw8k[twi];
            float2 w2 = g_tw8k[2 * twi];
            float2 w3 = cmul(w1, w2);
            zs[base]         = make_float2(t0.x + t2.x, t0.y + t2.y);
            zs[base + s]     = cmul(make_float2(t1.x + t3.x, t1.y + t3.y), w1);
            zs[base + 2 * s] = cmul(make_float2(t0.x - t2.x, t0.y - t2.y), w2);
            zs[base + 3 * s] = cmul(make_float2(t1.x - t3.x, t1.y - t3.y), w3);
        }
        __syncthreads();
    }
    /* final radix-2, adjacent pairs, no twiddle */
    for (int j = tid; j < 4096; j += FFT_THREADS) {
        int i0 = 2 * j;
        float2 a = zs[i0], b = zs[i0 + 1];
        zs[i0]     = make_float2(a.x + b.x, a.y + b.y);
        zs[i0 + 1] = make_float2(a.x - b.x, a.y - b.y);
    }
    __syncthreads();
}
/* inverse DIT (conj twiddles): digit-permuted input -> natural output, x8192 scale */
__device__ __forceinline__ void fft8k_r4_dit_inv(float2* zs, int tid) {
    for (int j = tid; j < 4096; j += FFT_THREADS) {
        int i0 = 2 * j;
        float2 a = zs[i0], b = zs[i0 + 1];
        zs[i0]     = make_float2(a.x + b.x, a.y + b.y);
        zs[i0 + 1] = make_float2(a.x - b.x, a.y - b.y);
    }
    __syncthreads();
    #pragma unroll
    for (int ls = 1; ls <= 11; ls += 2) {
        int s = 1 << ls;
        for (int j = tid; j < 2048; j += FFT_THREADS) {
            int o = j & (s - 1);
            int base = ((j >> ls) << (ls + 2)) + o;
            float2 A = zs[base], B = zs[base + s], C = zs[base + 2 * s], D = zs[base + 3 * s];
            int twi = o << (11 - ls);
            float2 w1 = g_tw8k[twi];
            float2 w2 = g_tw8k[2 * twi];
            float2 w3 = cmul(w1, w2);
            float2 u1 = cmulc(B, w1);
            float2 u2 = cmulc(C, w2);
            float2 u3 = cmulc(D, w3);
            float2 s0 = make_float2(A.x + u2.x, A.y + u2.y);
            float2 s1 = make_float2(A.x - u2.x, A.y - u2.y);
            float2 s2 = make_float2(u1.x + u3.x, u1.y + u3.y);
            float2 s3 = make_float2(-(u1.y - u3.y), u1.x - u3.x); /* i(u1-u3) */
            zs[base]         = make_float2(s0.x + s2.x, s0.y + s2.y);
            zs[base + s]     = make_float2(s1.x + s3.x, s1.y + s3.y);
            zs[base + 2 * s] = make_float2(s0.x - s2.x, s0.y - s2.y);
            zs[base + 3 * s] = make_float2(s1.x - s3.x, s1.y - s3.y);
        }
        __syncthreads();
    }
}

/* ---------------- filter FFT ---------------- */
__global__ void hf_kernel() {
    extern __shared__ float2 zs[];
    int d = blockIdx.x;
    int tid = threadIdx.x;
    const float2* hr = (const float2*)(g_h + (size_t)d * LSEQ);
    for (int n = tid; n < 4096; n += FFT_THREADS) zs[n] = hr[n];
    for (int n = 4096 + tid; n < NF; n += FFT_THREADS) zs[n] = make_float2(0.f, 0.f);
    __syncthreads();
    fft8k_r4_dif(zs, tid);
    float2* Hf = g_Hf + (size_t)d * 8193;
    for (int k = tid; k <= 4096; k += FFT_THREADS) {
        if (k == 0) {
            float2 Z0 = zs[0];
            Hf[0]    = make_float2(Z0.x + Z0.y, 0.f);
            Hf[8192] = make_float2(Z0.x - Z0.y, 0.f);
        } else if (k == 4096) {
            float2 Z = zs[1]; /* perm13(4096)=1 */
            Hf[4096] = make_float2(Z.x, -Z.y);
        } else {
            float2 Za = zs[perm13(k)], Zb = zs[perm13(8192 - k)];
            float2 Xe = make_float2(0.5f * (Za.x + Zb.x), 0.5f * (Za.y - Zb.y));
            float2 dd = make_float2(Za.x - Zb.x, Za.y + Zb.y);
            float2 Xo = make_float2(0.5f * dd.y, -0.5f * dd.x);
            float2 w  = g_u16[k];
            float2 wXo = cmul(w, Xo);
            Hf[k]        = make_float2(Xe.x + wXo.x, Xe.y + wXo.y);
            float2 Xm    = make_float2(Xe.x - wXo.x, Xe.y - wXo.y);
            Hf[8192 - k] = make_float2(Xm.x, -Xm.y);
        }
    }
}

/* ------------- conv FFT: y = irfft16384( rfft16384(v) * Hf )[:8192] ---- */
__global__ void conv_fft_kernel(const float* __restrict__ v, float* __restrict__ yout) {
    extern __shared__ float2 zs[];
    int bd = blockIdx.x;
    int d = bd & (DM - 1);
    int tid = threadIdx.x;
    const float2* vr = (const float2*)(v + (size_t)bd * LSEQ);
    for (int n = tid; n < 4096; n += FFT_THREADS) zs[n] = vr[n];
    for (int n = 4096 + tid; n < NF; n += FFT_THREADS) zs[n] = make_float2(0.f, 0.f);
    __syncthreads();
    fft8k_r4_dif(zs, tid);
    const float2* Hf = g_Hf + (size_t)d * 8193;
    for (int k = tid; k <= 4096; k += FFT_THREADS) {
        if (k == 0) {
            float2 Z0 = zs[0];
            float X0 = Z0.x + Z0.y, XN = Z0.x - Z0.y;
            float2 H0 = Hf[0], HN = Hf[8192];
            float2 P0 = make_float2(X0 * H0.x, X0 * H0.y);
            float2 PN = make_float2(XN * HN.x, XN * HN.y);
            float2 Xe2 = make_float2(0.5f * (P0.x + PN.x), 0.5f * (P0.y - PN.y));
            float2 Xo2 = make_float2(0.5f * (P0.x - PN.x), 0.5f * (P0.y + PN.y));
            zs[0] = make_float2(Xe2.x - Xo2.y, Xe2.y + Xo2.x);
        } else if (k == 4096) {
            float2 Z = zs[1];
            float2 H = Hf[4096];
            zs[1] = make_float2(Z.x * H.x + Z.y * H.y, Z.y * H.x - Z.x * H.y);
        } else {
            int p1 = perm13(k), p2 = perm13(8192 - k);
            float2 Za = zs[p1], Zb = zs[p2];
            float2 Xe = make_float2(0.5f * (Za.x + Zb.x), 0.5f * (Za.y - Zb.y));
            float2 dd = make_float2(Za.x - Zb.x, Za.y + Zb.y);
            float2 Xo = make_float2(0.5f * dd.y, -0.5f * dd.x);
            float2 w  = g_u16[k];
            float2 wXo = cmul(w, Xo);
            float2 Xp = make_float2(Xe.x + wXo.x, Xe.y + wXo.y);
            float2 Xm = make_float2(Xe.x - wXo.x, Xe.y - wXo.y);
            float2 Hk = Hf[k], Hn = Hf[8192 - k];
            float2 P1 = cmul(Xp, Hk);
            float2 Q  = cmul(Xm, make_float2(Hn.x, -Hn.y));
            float2 Xe2 = make_float2(0.5f * (P1.x + Q.x), 0.5f * (P1.y + Q.y));
            float2 pmq = make_float2(P1.x - Q.x, P1.y - Q.y);
            float2 Xo2 = cmul(make_float2(w.x, -w.y), pmq);
            Xo2.x *= 0.5f; Xo2.y *= 0.5f;
            zs[p1] = make_float2(Xe2.x - Xo2.y, Xe2.y + Xo2.x);
            zs[p2] = make_float2(Xe2.x + Xo2.y, Xo2.x - Xe2.y);
        }
    }
    __syncthreads();
    fft8k_r4_dit_inv(zs, tid);
    float2* yr = (float2*)(yout + (size_t)bd * LSEQ);
    const float sc = 1.0f / (float)NF;
    for (int n = tid; n < 4096; n += FFT_THREADS) {
        float2 t = zs[n];
        yr[n] = make_float2(t.x * sc, t.y * sc);
    }
}

/* ---------------- bf16 split-precision tensor-core GEMM ------------------------ */
/* C[M][N] = A[M][K] @ W[N][K]^T + bias.  A is fp32 (split to hi/lo in staging),  */
/* W pre-split to bf16 hi/lo.  128x128 CTA tile, BK=32, 8 warps, mma.m16n8k16.   */
/* Register-prefetch pipeline hides global latency under the MMA chain.          */
/* EPI=0: C row-major.  EPI=1: transposed into v/g0/g1 [b][d][l], bias folded.   */
__device__ __forceinline__ void mma_bf16(float c[4], const unsigned a[4],
                                         unsigned b0, unsigned b1) {
    asm volatile(
        "mma.sync.aligned.m16n8k16.row.col.f32.bf16.bf16.f32 "
        "{%0,%1,%2,%3}, {%4,%5,%6,%7}, {%8,%9}, {%0,%1,%2,%3};\n"
        : "+f"(c[0]), "+f"(c[1]), "+f"(c[2]), "+f"(c[3])
        : "r"(a[0]), "r"(a[1]), "r"(a[2]), "r"(a[3]), "r"(b0), "r"(b1));
}

template <int EPI>
__global__ void __launch_bounds__(256) mma_gemm_kernel(
    const float* __restrict__ A,
    const __nv_bfloat16* __restrict__ Bhi, const __nv_bfloat16* __restrict__ Blo,
    const float* __restrict__ bias,
    float* __restrict__ C0p, float* __restrict__ C1p, float* __restrict__ C2p,
    int M, int N, int K) {
    extern __shared__ char smraw[];
    __nv_bfloat16* sAhi = (__nv_bfloat16*)smraw;            /* [128][BKP] */
    __nv_bfloat16* sAlo = sAhi + 128 * BKP;
    __nv_bfloat16* sBhi = sAlo + 128 * BKP;
    __nv_bfloat16* sBlo = sBhi + 128 * BKP;
    float* ep = (float*)smraw;                              /* [128][132] staging */

    int tid = threadIdx.x;
    int warp = tid >> 5, lane = tid & 31;
    int gid = lane >> 2, tig = lane & 3;
    int warp_m = (warp >> 1) * 32;   /* 0,32,64,96 */
    int warp_n = (warp & 1) * 64;    /* 0,64       */
    int m0 = blockIdx.y * 128, n0 = blockIdx.x * 128;
    const float4* gA = (const float4*)A;
    const uint4* gBh = (const uint4*)Bhi;
    const uint4* gBl = (const uint4*)Blo;
    int ldvA = K >> 2;               /* float4 per A row */
    int ldvB = K >> 3;               /* uint4 per B row  */

    float acc[2][8][4];
    #pragma unroll
    for (int mt = 0; mt < 2; mt++)
        #pragma unroll
        for (int nt = 0; nt < 8; nt++)
            #pragma unroll
            for (int q = 0; q < 4; q++) acc[mt][nt][q] = 0.f;

    float4 rA[4];
    uint4  rBh[2], rBl[2];

    auto load_tile = [&](int k0) {
        int kqa = k0 >> 2, kqb = k0 >> 3;
        #pragma unroll
        for (int i = 0; i < 4; i++) {
            int idx = tid + i * 256;
            int row = idx >> 3, kq = idx & 7;
            rA[i] = gA[(size_t)(m0 + row) * ldvA + kqa + kq];
        }
        #pragma unroll
        for (int i = 0; i < 2; i++) {
            int idx = tid + i * 256;
            int row = idx >> 2, kq = idx & 3;
            rBh[i] = gBh[(size_t)(n0 + row) * ldvB + kqb + kq];
            rBl[i] = gBl[(size_t)(n0 + row) * ldvB + kqb + kq];
        }
    };
    auto store_tile = [&]() {
        #pragma unroll
        for (int i = 0; i < 4; i++) {
            int idx = tid + i * 256;
            int row = idx >> 3, kq = idx & 7;
            float4 v = rA[i];
            __nv_bfloat16 h0 = __float2bfloat16_rn(v.x);
            __nv_bfloat16 h1 = __float2bfloat16_rn(v.y);
            __nv_bfloat16 h2 = __float2bfloat16_rn(v.z);
            __nv_bfloat16 h3 = __float2bfloat16_rn(v.w);
            __nv_bfloat162 ph01; ph01.x = h0; ph01.y = h1;
            __nv_bfloat162 ph23; ph23.x = h2; ph23.y = h3;
            int off = row * BKP + kq * 4;
            *(__nv_bfloat162*)&sAhi[off]     = ph01;
            *(__nv_bfloat162*)&sAhi[off + 2] = ph23;
            __nv_bfloat162 pl01, pl23;
            pl01.x = __float2bfloat16_rn(v.x - __bfloat162float(h0));
            pl01.y = __float2bfloat16_rn(v.y - __bfloat162float(h1));
            pl23.x = __float2bfloat16_rn(v.z - __bfloat162float(h2));
            pl23.y = __float2bfloat16_rn(v.w - __bfloat162float(h3));
            *(__nv_bfloat162*)&sAlo[off]     = pl01;
            *(__nv_bfloat162*)&sAlo[off + 2] = pl23;
        }
        #pragma unroll
        for (int i = 0; i < 2; i++) {
            int idx = tid + i * 256;
            int row = idx >> 2, kq = idx & 3;
            *(uint4*)&sBhi[row * BKP + kq * 8] = rBh[i];
            *(uint4*)&sBlo[row * BKP + kq * 8] = rBl[i];
        }
    };

    load_tile(0);
    for (int k0 = 0; k0 < K; k0 += 32) {
        __syncthreads();
        store_tile();
        __syncthreads();
        if (k0 + 32 < K) load_tile(k0 + 32);
        #pragma unroll
        for (int k16 = 0; k16 < 32; k16 += 16) {
            unsigned ah[2][4], al[2][4];
            #pragma unroll
            for (int mt = 0; mt < 2; mt++) {
                int base = (warp_m + mt * 16 + gid) * BKP + k16 + 2 * tig;
                ah[mt][0] = *(const unsigned*)&sAhi[base];
                ah[mt][1] = *(const unsigned*)&sAhi[base + 8 * BKP];
                ah[mt][2] = *(const unsigned*)&sAhi[base + 8];
                ah[mt][3] = *(const unsigned*)&sAhi[base + 8 * BKP + 8];
                al[mt][0] = *(const unsigned*)&sAlo[base];
                al[mt][1] = *(const unsigned*)&sAlo[base + 8 * BKP];
                al[mt][2] = *(const unsigned*)&sAlo[base + 8];
                al[mt][3] = *(const unsigned*)&sAlo[base + 8 * BKP + 8];
            }
            #pragma unroll
            for (int nt = 0; nt < 8; nt++) {
                int cbase = (warp_n + nt * 8 + gid) * BKP + k16 + 2 * tig;
                unsigned bh0 = *(const unsigned*)&sBhi[cbase];
                unsigned bh1 = *(const unsigned*)&sBhi[cbase + 8];
                unsigned bl0 = *(const unsigned*)&sBlo[cbase];
                unsigned bl1 = *(const unsigned*)&sBlo[cbase + 8];
                #pragma unroll
                for (int mt = 0; mt < 2; mt++) {
                    mma_bf16(acc[mt][nt], ah[mt], bh0, bh1);
                    mma_bf16(acc[mt][nt], ah[mt], bl0, bl1);
                    mma_bf16(acc[mt][nt], al[mt], bh0, bh1);
                }
            }
        }
    }

    if (EPI == 0) {
        #pragma unroll
        for (int mt = 0; mt < 2; mt++) {
            #pragma unroll
            for (int nt = 0; nt < 8; nt++) {
                int r = m0 + warp_m + mt * 16 + gid;
                int c = n0 + warp_n + nt * 8 + 2 * tig;
                float b0v = bias[c], b1v = bias[c + 1];
                float2 w0 = make_float2(acc[mt][nt][0] + b0v, acc[mt][nt][1] + b1v);
                float2 w1 = make_float2(acc[mt][nt][2] + b0v, acc[mt][nt][3] + b1v);
                *(float2*)&C0p[(size_t)r * N + c] = w0;
                *(float2*)&C0p[(size_t)(r + 8) * N + c] = w1;
            }
        }
    } else {
        /* transposed epilogue -> v/g0/g1 in [b][d][l] layout, bias folded in */
        __syncthreads();
        #pragma unroll
        for (int mt = 0; mt < 2; mt++) {
            #pragma unroll
            for (int nt = 0; nt < 8; nt++) {
                int rl = warp_m + mt * 16 + gid;
                int cl = warp_n + nt * 8 + 2 * tig;
                ep[(size_t)cl * 132 + rl]           = acc[mt][nt][0];
                ep[(size_t)(cl + 1) * 132 + rl]     = acc[mt][nt][1];
                ep[(size_t)cl * 132 + rl + 8]       = acc[mt][nt][2];
                ep[(size_t)(cl + 1) * 132 + rl + 8] = acc[mt][nt][3];
            }
        }
        __syncthreads();
        int b = m0 >> 13;
        int l0 = m0 & (LSEQ - 1);
        int branch = n0 >> 8;
        int cc0 = n0 & 255;
        float* out = (branch == 0) ? C0p : ((branch == 1) ? C1p : C2p);
        for (int i = tid; i < 16384; i += 256) {
            int c = i >> 7, l = i & 127;
            out[((size_t)b * DM + cc0 + c) * LSEQ + l0 + l] = ep[c * 132 + l] + bias[n0 + c];
        }
    }
}

/* -------- gating: gated[b][l][d] = y * dwconv(g0) * dwconv(g1), fp32 ---------- */
__global__ void gate_kernel(const float* __restrict__ yv, const float* __restrict__ g0r,
                            const float* __restrict__ g1r,
                            const float* __restrict__ w0, const float* __restrict__ b0,
                            const float* __restrict__ w1, const float* __restrict__ b1,
                            float* __restrict__ gated) {
    __shared__ float s0[32][34];
    __shared__ float s1[32][34];
    __shared__ float sy[32][33];
    __shared__ float so[32][33]; /* [l][d] staging */
    int b = blockIdx.z;
    int d0 = blockIdx.y * 32;
    int l0 = blockIdx.x * 32;
    int x = threadIdx.x, y = threadIdx.y;
    size_t base = ((size_t)b * DM + d0) * LSEQ + l0;
    for (int i = y; i < 32; i += 8) {
        size_t row = base + (size_t)i * LSEQ;
        s0[i][x + 1] = g0r[row + x];
        s1[i][x + 1] = g1r[row + x];
        sy[i][x] = yv[row + x];
    }
    if (x == 0) {
        for (int i = y; i < 32; i += 8) {
            size_t row = base + (size_t)i * LSEQ;
            s0[i][0] = (l0 > 0) ? g0r[row - 1] : 0.f;
            s1[i][0] = (l0 > 0) ? g1r[row - 1] : 0.f;
        }
    }
    if (x == 31) {
        for (int i = y; i < 32; i += 8) {
            size_t row = base + (size_t)i * LSEQ;
            s0[i][33] = (l0 + 32 < LSEQ) ? g0r[row + 32] : 0.f;
            s1[i][33] = (l0 + 32 < LSEQ) ? g1r[row + 32] : 0.f;
        }
    }
    __syncthreads();
    for (int i = y; i < 32; i += 8) {
        int d = d0 + i;
        float c0v = w0[d * 3 + 0] * s0[i][x] + w0[d * 3 + 1] * s0[i][x + 1] +
                    w0[d * 3 + 2] * s0[i][x + 2] + b0[d];
        float c1v = w1[d * 3 + 0] * s1[i][x] + w1[d * 3 + 1] * s1[i][x + 1] +
                    w1[d * 3 + 2] * s1[i][x + 2] + b1[d];
        so[x][i] = sy[i][x] * c0v * c1v;
    }
    __syncthreads();
    size_t ob = ((size_t)b * LSEQ + l0) * DM + d0;
    for (int i = y; i < 32; i += 8) gated[ob + (size_t)i * DM + x] = so[i][x];
}

/* ---------------- launch ---------------- */
extern "C" void kernel_launch(void* const* d_in, const int* in_sizes, int n_in,
                              void* d_out, int out_size) {
    const float* x       = (const float*)d_in[0];
    const float* in_W    = (const float*)d_in[1];
    const float* in_b    = (const float*)d_in[2];
    const float* conv0_W = (const float*)d_in[3];
    const float* conv0_b = (const float*)d_in[4];
    const float* conv1_W = (const float*)d_in[5];
    const float* conv1_b = (const float*)d_in[6];
    const float* mlp_W1  = (const float*)d_in[7];
    const float* mlp_b1  = (const float*)d_in[8];
    const float* mlp_W2  = (const float*)d_in[9];
    const float* mlp_b2  = (const float*)d_in[10];
    const float* out_W   = (const float*)d_in[11];
    const float* out_b   = (const float*)d_in[12];
    const float* t       = (const float*)d_in[13];
    float* out = (float*)d_out;

    cudaFuncSetAttribute(conv_fft_kernel, cudaFuncAttributeMaxDynamicSharedMemorySize, 65536);
    cudaFuncSetAttribute(hf_kernel,       cudaFuncAttributeMaxDynamicSharedMemorySize, 65536);
    cudaFuncSetAttribute(mma_gemm_kernel<1>, cudaFuncAttributeMaxDynamicSharedMemorySize, 128 * 132 * 4);
    cudaFuncSetAttribute(mma_gemm_kernel<0>, cudaFuncAttributeMaxDynamicSharedMemorySize, 4 * 128 * BKP * 2);

    __nv_bfloat16 *pW1hi, *pW1lo, *pW2hi, *pW2lo;
    cudaGetSymbolAddress((void**)&pW1hi, g_W1hi);
    cudaGetSymbolAddress((void**)&pW1lo, g_W1lo);
    cudaGetSymbolAddress((void**)&pW2hi, g_W2hi);
    cudaGetSymbolAddress((void**)&pW2lo, g_W2lo);
    float *pV, *pG0, *pG1, *pYc, *pGated;
    cudaGetSymbolAddress((void**)&pV,     g_v);
    cudaGetSymbolAddress((void**)&pG0,    g_g0);
    cudaGetSymbolAddress((void**)&pG1,    g_g1);
    cudaGetSymbolAddress((void**)&pYc,    g_yc);
    cudaGetSymbolAddress((void**)&pGated, g_gated);

    const int M = BATCH * LSEQ;

    init_tables_kernel<<<(8193 + 255) / 256, 256>>>();
    split_bf16_kernel<<<(768 * 256 / 4 + 255) / 256, 256>>>(in_W, pW1hi, pW1lo, 768 * 256);
    split_bf16_kernel<<<(256 * 256 / 4 + 255) / 256, 256>>>(out_W, pW2hi, pW2lo, 256 * 256);
    sact_kernel<<<(64 * LSEQ + 255) / 256, 256>>>(t, mlp_W1, mlp_b1);
    hmix_kernel<<<LSEQ / 128, 128>>>(mlp_W2, mlp_b2);
    hf_kernel<<<DM, FFT_THREADS, 65536>>>();

    /* in-proj: A = x fp32 (split in staging); epilogue writes v/g0/g1 transposed */
    mma_gemm_kernel<1><<<dim3(768 / 128, M / 128), 256, 128 * 132 * 4>>>(
        x, pW1hi, pW1lo, in_b, pV, pG0, pG1, M, 768, 256);

    conv_fft_kernel<<<BATCH * DM, FFT_THREADS, 65536>>>(pV, pYc);
    gate_kernel<<<dim3(LSEQ / 32, DM / 32, BATCH), dim3(32, 8)>>>(
        pYc, pG0, pG1, conv0_W, conv0_b, conv1_W, conv1_b, pGated);

    /* out-proj */
    mma_gemm_kernel<0><<<dim3(256 / 128, M / 128), 256, 4 * 128 * BKP * 2>>>(
        pGated, pW2hi, pW2lo, out_b, out, nullptr, nullptr, M, 256, 256);

    (void)in_sizes; (void)n_in; (void)out_size;
}